// round 1
// baseline (speedup 1.0000x reference)
#include <cuda_runtime.h>

#define C_DIM   1024
#define NSEQ    2048
#define NHEADS  16
#define HDIM    64
#define BATCH   2
#define ROWS    (BATCH * NSEQ)       // 4096
#define ATT_SCALE 0.125f             // 1/sqrt(64)

// Scratch (no allocations allowed in kernel_launch)
__device__ float g_qkv[ROWS * 3 * C_DIM];   // [4096, 3072]
__device__ float g_att[ROWS * C_DIM];       // [4096, 1024]

// ---------------------------------------------------------------------------
// NT GEMM with bias:  C[M,Nt] = A[M,K] @ W[Nt,K]^T + bias[Nt]
// 128x128 block tile, TK=16, 256 threads, 8x8 microtile.
// ---------------------------------------------------------------------------
__global__ __launch_bounds__(256, 2)
void gemm_nt_bias(const float* __restrict__ A, const float* __restrict__ W,
                  const float* __restrict__ bias, float* __restrict__ Cout,
                  int M, int Nt, int K)
{
    __shared__ float As[16][128];
    __shared__ float Bs[16][128];

    const int t  = threadIdx.x;
    const int tx = t & 15;          // 0..15 -> n microtile
    const int ty = t >> 4;          // 0..15 -> m microtile
    const int m0 = blockIdx.y << 7;
    const int n0 = blockIdx.x << 7;

    float acc[8][8];
#pragma unroll
    for (int i = 0; i < 8; i++)
#pragma unroll
        for (int j = 0; j < 8; j++) acc[i][j] = 0.f;

    // Load mapping: 128 rows x 16 k per step; 4 lanes per row (64B/row).
    const int row0 = t >> 2;            // 0..63
    const int kq0  = (t & 3) << 2;      // 0,4,8,12
    const float* Ap0 = A + (m0 + row0)      * K + kq0;
    const float* Ap1 = A + (m0 + row0 + 64) * K + kq0;
    const float* Wp0 = W + (n0 + row0)      * K + kq0;
    const float* Wp1 = W + (n0 + row0 + 64) * K + kq0;

    for (int k0 = 0; k0 < K; k0 += 16) {
        float4 a0 = *(const float4*)(Ap0 + k0);
        float4 a1 = *(const float4*)(Ap1 + k0);
        float4 w0 = *(const float4*)(Wp0 + k0);
        float4 w1 = *(const float4*)(Wp1 + k0);
        __syncthreads();   // previous compute done before overwriting smem
        As[kq0 + 0][row0] = a0.x; As[kq0 + 1][row0] = a0.y;
        As[kq0 + 2][row0] = a0.z; As[kq0 + 3][row0] = a0.w;
        As[kq0 + 0][row0 + 64] = a1.x; As[kq0 + 1][row0 + 64] = a1.y;
        As[kq0 + 2][row0 + 64] = a1.z; As[kq0 + 3][row0 + 64] = a1.w;
        Bs[kq0 + 0][row0] = w0.x; Bs[kq0 + 1][row0] = w0.y;
        Bs[kq0 + 2][row0] = w0.z; Bs[kq0 + 3][row0] = w0.w;
        Bs[kq0 + 0][row0 + 64] = w1.x; Bs[kq0 + 1][row0 + 64] = w1.y;
        Bs[kq0 + 2][row0 + 64] = w1.z; Bs[kq0 + 3][row0 + 64] = w1.w;
        __syncthreads();

#pragma unroll
        for (int kk = 0; kk < 16; kk++) {
            float4 av0 = *(const float4*)&As[kk][ty * 8];
            float4 av1 = *(const float4*)&As[kk][ty * 8 + 4];
            float4 bv0 = *(const float4*)&Bs[kk][tx * 8];
            float4 bv1 = *(const float4*)&Bs[kk][tx * 8 + 4];
            float a[8] = {av0.x, av0.y, av0.z, av0.w, av1.x, av1.y, av1.z, av1.w};
            float b[8] = {bv0.x, bv0.y, bv0.z, bv0.w, bv1.x, bv1.y, bv1.z, bv1.w};
#pragma unroll
            for (int i = 0; i < 8; i++)
#pragma unroll
                for (int j = 0; j < 8; j++)
                    acc[i][j] = fmaf(a[i], b[j], acc[i][j]);
        }
    }

    // Epilogue: add bias, store
    float bb[8];
#pragma unroll
    for (int j = 0; j < 8; j++) bb[j] = bias[n0 + tx * 8 + j];
#pragma unroll
    for (int i = 0; i < 8; i++) {
        float* crow = Cout + (m0 + ty * 8 + i) * Nt + n0 + tx * 8;
        float4 o0, o1;
        o0.x = acc[i][0] + bb[0]; o0.y = acc[i][1] + bb[1];
        o0.z = acc[i][2] + bb[2]; o0.w = acc[i][3] + bb[3];
        o1.x = acc[i][4] + bb[4]; o1.y = acc[i][5] + bb[5];
        o1.z = acc[i][6] + bb[6]; o1.w = acc[i][7] + bb[7];
        *(float4*)(crow)     = o0;
        *(float4*)(crow + 4) = o1;
    }
}

// ---------------------------------------------------------------------------
// Fused flash-style attention.
// grid: (NSEQ/64 query tiles, BATCH*NHEADS). 256 threads (16x16).
// Each block: 64 queries x D=64, loops over 32 key tiles of 64.
// qkv layout: [B, N, 3, H, D] flattened -> element (b,n,s,h,d) at
//   ((b*NSEQ + n)*3 + s)*C_DIM + h*HDIM + d
// ---------------------------------------------------------------------------
__global__ __launch_bounds__(256)
void attn_kernel(const float* __restrict__ qkv, float* __restrict__ out)
{
    extern __shared__ float sm[];
    float* Qt = sm;               // [64][64]  Qt[d*64 + r]        (d-major)
    float* KP = sm + 64 * 64;     // [64][65]  Ks[c*65 + d]  /  Ps[r*65 + c]
    float* Vs = KP + 64 * 65;     // [64][64]  Vs[c*64 + d]

    const int t  = threadIdx.x;
    const int tx = t & 15;        // col group
    const int ty = t >> 4;        // row group
    const int q0 = blockIdx.x * 64;
    const int bh = blockIdx.y;
    const int b  = bh >> 4;
    const int h  = bh & 15;
    const int rstride = 3 * C_DIM;   // 3072

    const float* qbase = qkv + ((b * NSEQ + q0) * 3 + 0) * C_DIM + h * HDIM;
    const float* kbase = qkv + ((b * NSEQ) * 3 + 1) * C_DIM + h * HDIM;
    const float* vbase = qkv + ((b * NSEQ) * 3 + 2) * C_DIM + h * HDIM;

    // Load Q tile transposed (d-major)
#pragma unroll
    for (int i = 0; i < 4; i++) {
        int f  = t + i * 256;        // 0..1023 float4 slots
        int r  = f >> 4;
        int d4 = (f & 15) << 2;
        float4 v = *(const float4*)(qbase + r * rstride + d4);
        Qt[(d4 + 0) * 64 + r] = v.x;
        Qt[(d4 + 1) * 64 + r] = v.y;
        Qt[(d4 + 2) * 64 + r] = v.z;
        Qt[(d4 + 3) * 64 + r] = v.w;
    }

    float m_run[4], l_run[4], o[4][4];
#pragma unroll
    for (int i = 0; i < 4; i++) {
        m_run[i] = -1e30f; l_run[i] = 0.f;
#pragma unroll
        for (int j = 0; j < 4; j++) o[i][j] = 0.f;
    }

    for (int kt = 0; kt < NSEQ / 64; kt++) {
        __syncthreads();   // previous iteration's reads of KP/Vs done (also covers Qt load)
        const float* kb = kbase + (kt * 64) * rstride;
        const float* vb = vbase + (kt * 64) * rstride;
#pragma unroll
        for (int i = 0; i < 4; i++) {
            int f  = t + i * 256;
            int c  = f >> 4;
            int d4 = (f & 15) << 2;
            float4 kv = *(const float4*)(kb + c * rstride + d4);
            KP[c * 65 + d4 + 0] = kv.x;
            KP[c * 65 + d4 + 1] = kv.y;
            KP[c * 65 + d4 + 2] = kv.z;
            KP[c * 65 + d4 + 3] = kv.w;
            float4 vv = *(const float4*)(vb + c * rstride + d4);
            *(float4*)&Vs[c * 64 + d4] = vv;
        }
        __syncthreads();

        // S = Q @ K^T   (64x64 tile; thread owns rows ty*4.., cols tx*4..)
        float s[4][4];
#pragma unroll
        for (int i = 0; i < 4; i++)
#pragma unroll
            for (int j = 0; j < 4; j++) s[i][j] = 0.f;

#pragma unroll 8
        for (int d = 0; d < 64; d++) {
            float4 a = *(const float4*)&Qt[d * 64 + ty * 4];
            float b0 = KP[(tx * 4 + 0) * 65 + d];
            float b1 = KP[(tx * 4 + 1) * 65 + d];
            float b2 = KP[(tx * 4 + 2) * 65 + d];
            float b3 = KP[(tx * 4 + 3) * 65 + d];
            s[0][0] = fmaf(a.x, b0, s[0][0]); s[0][1] = fmaf(a.x, b1, s[0][1]);
            s[0][2] = fmaf(a.x, b2, s[0][2]); s[0][3] = fmaf(a.x, b3, s[0][3]);
            s[1][0] = fmaf(a.y, b0, s[1][0]); s[1][1] = fmaf(a.y, b1, s[1][1]);
            s[1][2] = fmaf(a.y, b2, s[1][2]); s[1][3] = fmaf(a.y, b3, s[1][3]);
            s[2][0] = fmaf(a.z, b0, s[2][0]); s[2][1] = fmaf(a.z, b1, s[2][1]);
            s[2][2] = fmaf(a.z, b2, s[2][2]); s[2][3] = fmaf(a.z, b3, s[2][3]);
            s[3][0] = fmaf(a.w, b0, s[3][0]); s[3][1] = fmaf(a.w, b1, s[3][1]);
            s[3][2] = fmaf(a.w, b2, s[3][2]); s[3][3] = fmaf(a.w, b3, s[3][3]);
        }

        // Online softmax update. Lanes sharing ty form a 16-lane shuffle group
        // (t = ty*16 + tx -> contiguous within a warp half).
        float p[4][4];
#pragma unroll
        for (int i = 0; i < 4; i++) {
#pragma unroll
            for (int j = 0; j < 4; j++) s[i][j] *= ATT_SCALE;
            float mt = fmaxf(fmaxf(s[i][0], s[i][1]), fmaxf(s[i][2], s[i][3]));
#pragma unroll
            for (int off = 8; off >= 1; off >>= 1)
                mt = fmaxf(mt, __shfl_xor_sync(0xffffffffu, mt, off));
            float m_new = fmaxf(m_run[i], mt);
            float corr  = __expf(m_run[i] - m_new);
            m_run[i] = m_new;
            float rs = 0.f;
#pragma unroll
            for (int j = 0; j < 4; j++) {
                p[i][j] = __expf(s[i][j] - m_new);
                rs += p[i][j];
            }
#pragma unroll
            for (int off = 8; off >= 1; off >>= 1)
                rs += __shfl_xor_sync(0xffffffffu, rs, off);
            l_run[i] = l_run[i] * corr + rs;
#pragma unroll
            for (int j = 0; j < 4; j++) o[i][j] *= corr;
        }

        __syncthreads();   // all S reads of KP (as K) done
        // Write P into the K buffer (row-major, pitch 65)
#pragma unroll
        for (int i = 0; i < 4; i++)
#pragma unroll
            for (int j = 0; j < 4; j++)
                KP[(ty * 4 + i) * 65 + tx * 4 + j] = p[i][j];
        __syncthreads();

        // O += P @ V   (thread owns rows ty*4.., dims tx*4..)
#pragma unroll 8
        for (int c = 0; c < 64; c++) {
            float4 v = *(const float4*)&Vs[c * 64 + tx * 4];
            float p0 = KP[(ty * 4 + 0) * 65 + c];
            float p1 = KP[(ty * 4 + 1) * 65 + c];
            float p2 = KP[(ty * 4 + 2) * 65 + c];
            float p3 = KP[(ty * 4 + 3) * 65 + c];
            o[0][0] = fmaf(p0, v.x, o[0][0]); o[0][1] = fmaf(p0, v.y, o[0][1]);
            o[0][2] = fmaf(p0, v.z, o[0][2]); o[0][3] = fmaf(p0, v.w, o[0][3]);
            o[1][0] = fmaf(p1, v.x, o[1][0]); o[1][1] = fmaf(p1, v.y, o[1][1]);
            o[1][2] = fmaf(p1, v.z, o[1][2]); o[1][3] = fmaf(p1, v.w, o[1][3]);
            o[2][0] = fmaf(p2, v.x, o[2][0]); o[2][1] = fmaf(p2, v.y, o[2][1]);
            o[2][2] = fmaf(p2, v.z, o[2][2]); o[2][3] = fmaf(p2, v.w, o[2][3]);
            o[3][0] = fmaf(p3, v.x, o[3][0]); o[3][1] = fmaf(p3, v.y, o[3][1]);
            o[3][2] = fmaf(p3, v.z, o[3][2]); o[3][3] = fmaf(p3, v.w, o[3][3]);
        }
    }

    // Epilogue: normalize and store [4096, 1024] layout (row b*N+n, col h*64+d)
#pragma unroll
    for (int i = 0; i < 4; i++) {
        float inv = 1.f / l_run[i];
        float4 ov;
        ov.x = o[i][0] * inv; ov.y = o[i][1] * inv;
        ov.z = o[i][2] * inv; ov.w = o[i][3] * inv;
        *(float4*)(out + (b * NSEQ + q0 + ty * 4 + i) * C_DIM + h * HDIM + tx * 4) = ov;
    }
}

// ---------------------------------------------------------------------------
extern "C" void kernel_launch(void* const* d_in, const int* in_sizes, int n_in,
                              void* d_out, int out_size)
{
    const float* x      = (const float*)d_in[0];
    const float* w_qkv  = (const float*)d_in[1];
    const float* b_qkv  = (const float*)d_in[2];
    const float* w_proj = (const float*)d_in[3];
    const float* b_proj = (const float*)d_in[4];
    float* out = (float*)d_out;

    float *qkv_s, *att_s;
    cudaGetSymbolAddress((void**)&qkv_s, g_qkv);
    cudaGetSymbolAddress((void**)&att_s, g_att);

    const int attn_smem = (64 * 64 + 64 * 65 + 64 * 64) * (int)sizeof(float); // 49408
    cudaFuncSetAttribute(attn_kernel, cudaFuncAttributeMaxDynamicSharedMemorySize, attn_smem);

    // 1) QKV projection: [4096,1024] @ [3072,1024]^T + b -> [4096,3072]
    dim3 g1(3 * C_DIM / 128, ROWS / 128);
    gemm_nt_bias<<<g1, 256>>>(x, w_qkv, b_qkv, qkv_s, ROWS, 3 * C_DIM, C_DIM);

    // 2) Fused attention -> [4096,1024]
    dim3 g2(NSEQ / 64, BATCH * NHEADS);
    attn_kernel<<<g2, 256, attn_smem>>>(qkv_s, att_s);

    // 3) Output projection: [4096,1024] @ [1024,1024]^T + b -> out
    dim3 g3(C_DIM / 128, ROWS / 128);
    gemm_nt_bias<<<g3, 256>>>(att_s, w_proj, b_proj, out, ROWS, C_DIM, C_DIM);
}

// round 3
// speedup vs baseline: 1.3093x; 1.3093x over previous
#include <cuda_runtime.h>
#include <cstdint>

#define C_DIM   1024
#define NSEQ    2048
#define NHEADS  16
#define HDIM    64
#define BATCH   2
#define ROWS    (BATCH * NSEQ)       // 4096
#define ATT_SCALE 0.125f             // 1/sqrt(64)

// Scratch (no allocations allowed in kernel_launch)
__device__ float g_qkv[ROWS * 3 * C_DIM];   // [4096, 3072]
__device__ float g_att[ROWS * C_DIM];       // [4096, 1024]

// ===========================================================================
// tf32 helpers (arch-independent PTX: works on plain sm_103 target)
// ===========================================================================
__device__ __forceinline__ uint32_t f2tf32(float x) {
    uint32_t r;
    asm("cvt.rna.tf32.f32 %0, %1;" : "=r"(r) : "f"(x));
    return r;
}

// D += A @ B  for one m16n8k8 tf32 tile (A row-major, B col-major fragments)
__device__ __forceinline__ void mma_tf32(float* d, const uint32_t* a, const uint32_t* b) {
    asm volatile(
        "mma.sync.aligned.m16n8k8.row.col.f32.tf32.tf32.f32 "
        "{%0,%1,%2,%3}, {%4,%5,%6,%7}, {%8,%9}, {%0,%1,%2,%3};"
        : "+f"(d[0]), "+f"(d[1]), "+f"(d[2]), "+f"(d[3])
        : "r"(a[0]), "r"(a[1]), "r"(a[2]), "r"(a[3]), "r"(b[0]), "r"(b[1]));
}

// ===========================================================================
// tf32 mma.sync NT GEMM:  C[M,Nt] = A[M,K] @ W[Nt,K]^T + bias[Nt]
// 128x128 block tile, BK=32, 256 threads (8 warps, each 64x32).
// SMEM holds fragment-ordered tiles; double buffered.
//
// Fragment layouts (per BK=32 chunk):
//   Afrag[ks(4)][mt(8)][lane(32)][4]  floats  (16 KB)
//   Bfrag[ks(4)][nt(16)][lane(32)][2] floats  (16 KB)
// mma m16n8k8 mapping (lane = tid&31, r = lane>>2, c = lane&3):
//   a0=A[r,c] a1=A[r+8,c] a2=A[r,c+4] a3=A[r+8,c+4]   (within 16x8 tile)
//   b0=B[c, n=r] b1=B[c+4, n=r]                        (within 8k x 8n tile)
//   d0=C[r,2c] d1=C[r,2c+1] d2=C[r+8,2c] d3=C[r+8,2c+1]
// ===========================================================================
#define GBK 32
#define STAGE_BYTES 32768   // Afrag 16K + Bfrag 16K
#define GEMM_SMEM   (2 * STAGE_BYTES)

__global__ __launch_bounds__(256)
void gemm_mma_tf32(const float* __restrict__ A, const float* __restrict__ W,
                   const float* __restrict__ bias, float* __restrict__ Cout,
                   int M, int Nt, int K)
{
    extern __shared__ char smem[];
    const int t      = threadIdx.x;
    const int lane   = t & 31;
    const int wid    = t >> 5;
    const int warp_m = wid & 1;     // 2 warps over M
    const int warp_n = wid >> 1;    // 4 warps over N
    const int m0 = blockIdx.y << 7;
    const int n0 = blockIdx.x << 7;

    // Per-thread staging indices (constant across chunks)
    // gmem: fi = t + 256*p -> row = fi>>3 (0..127), c4 = (fi&7)*4 (0..28)
    float acc[4][4][4];
#pragma unroll
    for (int i = 0; i < 4; i++)
#pragma unroll
        for (int j = 0; j < 4; j++)
#pragma unroll
            for (int e = 0; e < 4; e++) acc[i][j][e] = 0.f;

    const int nch = K / GBK;
    float4 ra[4], rw[4];

    // ---- staging helpers (macros to keep everything in registers) ----
#define LOAD_GMEM(cidx)                                                        \
    {                                                                          \
        const float* Ap = A + (size_t)m0 * K + (cidx) * GBK;                   \
        const float* Wp = W + (size_t)n0 * K + (cidx) * GBK;                   \
        _Pragma("unroll")                                                      \
        for (int p = 0; p < 4; p++) {                                          \
            int fi = t + 256 * p;                                              \
            int row = fi >> 3;                                                 \
            int c4  = (fi & 7) << 2;                                           \
            ra[p] = *(const float4*)(Ap + row * K + c4);                       \
            rw[p] = *(const float4*)(Wp + row * K + c4);                       \
        }                                                                      \
    }

#define STORE_STAGE(s)                                                         \
    {                                                                          \
        uint32_t* Asf = (uint32_t*)(smem + (s) * STAGE_BYTES);                 \
        uint32_t* Bsf = (uint32_t*)(smem + (s) * STAGE_BYTES + 16384);         \
        _Pragma("unroll")                                                      \
        for (int p = 0; p < 4; p++) {                                          \
            int fi = t + 256 * p;                                              \
            int row = fi >> 3;                                                 \
            int c4  = (fi & 7) << 2;                                           \
            int ks  = c4 >> 3;                                                 \
            int khi = (c4 >> 2) & 1;                                           \
            /* A element (row, c4+e) */                                        \
            int mt = row >> 4, r = row & 15;                                   \
            uint32_t abase = (uint32_t)((((ks * 8 + mt) * 32 + (r & 7) * 4) << 2) \
                                        + (r >> 3) + (khi << 1));              \
            Asf[abase + 0]  = f2tf32(ra[p].x);                                 \
            Asf[abase + 4]  = f2tf32(ra[p].y);                                 \
            Asf[abase + 8]  = f2tf32(ra[p].z);                                 \
            Asf[abase + 12] = f2tf32(ra[p].w);                                 \
            /* B element (n=row, c4+e) */                                      \
            int nt = row >> 3, nl = row & 7;                                   \
            uint32_t bbase = (uint32_t)((((ks * 16 + nt) * 32 + nl * 4) << 1)  \
                                        + khi);                               \
            Bsf[bbase + 0] = f2tf32(rw[p].x);                                  \
            Bsf[bbase + 2] = f2tf32(rw[p].y);                                  \
            Bsf[bbase + 4] = f2tf32(rw[p].z);                                  \
            Bsf[bbase + 6] = f2tf32(rw[p].w);                                  \
        }                                                                      \
    }

    // Prologue: stage chunk 0
    LOAD_GMEM(0);
    STORE_STAGE(0);
    __syncthreads();

    for (int c = 0; c < nch; c++) {
        const int s = c & 1;
        if (c + 1 < nch) LOAD_GMEM(c + 1);

        const char* Ast = smem + s * STAGE_BYTES;
        const char* Bst = smem + s * STAGE_BYTES + 16384;
#pragma unroll
        for (int ks = 0; ks < 4; ks++) {
            uint32_t afr[4][4];
            uint32_t bfr[4][2];
#pragma unroll
            for (int mt = 0; mt < 4; mt++) {
                uint4 v = *(const uint4*)(Ast +
                    (((ks * 8 + warp_m * 4 + mt) * 32 + lane) << 4));
                afr[mt][0] = v.x; afr[mt][1] = v.y; afr[mt][2] = v.z; afr[mt][3] = v.w;
            }
#pragma unroll
            for (int nt = 0; nt < 4; nt++) {
                uint2 v = *(const uint2*)(Bst +
                    (((ks * 16 + warp_n * 4 + nt) * 32 + lane) << 3));
                bfr[nt][0] = v.x; bfr[nt][1] = v.y;
            }
#pragma unroll
            for (int mt = 0; mt < 4; mt++)
#pragma unroll
                for (int nt = 0; nt < 4; nt++)
                    mma_tf32(acc[mt][nt], afr[mt], bfr[nt]);
        }

        if (c + 1 < nch) {
            __syncthreads();
            STORE_STAGE(s ^ 1);
            __syncthreads();
        }
    }

    // Epilogue: direct stores with bias (float2 per half-tile)
    const int r  = lane >> 2;
    const int c2 = (lane & 3) << 1;
#pragma unroll
    for (int nt = 0; nt < 4; nt++) {
        const int gn = n0 + warp_n * 32 + nt * 8 + c2;
        const float b0 = bias[gn], b1 = bias[gn + 1];
#pragma unroll
        for (int mt = 0; mt < 4; mt++) {
            const int gm = m0 + warp_m * 64 + mt * 16 + r;
            float2 v0, v1;
            v0.x = acc[mt][nt][0] + b0; v0.y = acc[mt][nt][1] + b1;
            v1.x = acc[mt][nt][2] + b0; v1.y = acc[mt][nt][3] + b1;
            *(float2*)&Cout[(size_t)gm * Nt + gn]       = v0;
            *(float2*)&Cout[(size_t)(gm + 8) * Nt + gn] = v1;
        }
    }
#undef LOAD_GMEM
#undef STORE_STAGE
}

// ---------------------------------------------------------------------------
// Fused flash-style attention (fp32 SIMT — unchanged, ~900us).
// ---------------------------------------------------------------------------
__global__ __launch_bounds__(256)
void attn_kernel(const float* __restrict__ qkv, float* __restrict__ out)
{
    extern __shared__ float sm[];
    float* Qt = sm;               // [64][64]  Qt[d*64 + r]        (d-major)
    float* KP = sm + 64 * 64;     // [64][65]  Ks[c*65 + d]  /  Ps[r*65 + c]
    float* Vs = KP + 64 * 65;     // [64][64]  Vs[c*64 + d]

    const int t  = threadIdx.x;
    const int tx = t & 15;
    const int ty = t >> 4;
    const int q0 = blockIdx.x * 64;
    const int bh = blockIdx.y;
    const int b  = bh >> 4;
    const int h  = bh & 15;
    const int rstride = 3 * C_DIM;

    const float* qbase = qkv + ((b * NSEQ + q0) * 3 + 0) * C_DIM + h * HDIM;
    const float* kbase = qkv + ((b * NSEQ) * 3 + 1) * C_DIM + h * HDIM;
    const float* vbase = qkv + ((b * NSEQ) * 3 + 2) * C_DIM + h * HDIM;

#pragma unroll
    for (int i = 0; i < 4; i++) {
        int f  = t + i * 256;
        int r  = f >> 4;
        int d4 = (f & 15) << 2;
        float4 v = *(const float4*)(qbase + r * rstride + d4);
        Qt[(d4 + 0) * 64 + r] = v.x;
        Qt[(d4 + 1) * 64 + r] = v.y;
        Qt[(d4 + 2) * 64 + r] = v.z;
        Qt[(d4 + 3) * 64 + r] = v.w;
    }

    float m_run[4], l_run[4], o[4][4];
#pragma unroll
    for (int i = 0; i < 4; i++) {
        m_run[i] = -1e30f; l_run[i] = 0.f;
#pragma unroll
        for (int j = 0; j < 4; j++) o[i][j] = 0.f;
    }

    for (int kt = 0; kt < NSEQ / 64; kt++) {
        __syncthreads();
        const float* kb = kbase + (kt * 64) * rstride;
        const float* vb = vbase + (kt * 64) * rstride;
#pragma unroll
        for (int i = 0; i < 4; i++) {
            int f  = t + i * 256;
            int c  = f >> 4;
            int d4 = (f & 15) << 2;
            float4 kv = *(const float4*)(kb + c * rstride + d4);
            KP[c * 65 + d4 + 0] = kv.x;
            KP[c * 65 + d4 + 1] = kv.y;
            KP[c * 65 + d4 + 2] = kv.z;
            KP[c * 65 + d4 + 3] = kv.w;
            float4 vv = *(const float4*)(vb + c * rstride + d4);
            *(float4*)&Vs[c * 64 + d4] = vv;
        }
        __syncthreads();

        float s[4][4];
#pragma unroll
        for (int i = 0; i < 4; i++)
#pragma unroll
            for (int j = 0; j < 4; j++) s[i][j] = 0.f;

#pragma unroll 8
        for (int d = 0; d < 64; d++) {
            float4 a = *(const float4*)&Qt[d * 64 + ty * 4];
            float b0 = KP[(tx * 4 + 0) * 65 + d];
            float b1 = KP[(tx * 4 + 1) * 65 + d];
            float b2 = KP[(tx * 4 + 2) * 65 + d];
            float b3 = KP[(tx * 4 + 3) * 65 + d];
            s[0][0] = fmaf(a.x, b0, s[0][0]); s[0][1] = fmaf(a.x, b1, s[0][1]);
            s[0][2] = fmaf(a.x, b2, s[0][2]); s[0][3] = fmaf(a.x, b3, s[0][3]);
            s[1][0] = fmaf(a.y, b0, s[1][0]); s[1][1] = fmaf(a.y, b1, s[1][1]);
            s[1][2] = fmaf(a.y, b2, s[1][2]); s[1][3] = fmaf(a.y, b3, s[1][3]);
            s[2][0] = fmaf(a.z, b0, s[2][0]); s[2][1] = fmaf(a.z, b1, s[2][1]);
            s[2][2] = fmaf(a.z, b2, s[2][2]); s[2][3] = fmaf(a.z, b3, s[2][3]);
            s[3][0] = fmaf(a.w, b0, s[3][0]); s[3][1] = fmaf(a.w, b1, s[3][1]);
            s[3][2] = fmaf(a.w, b2, s[3][2]); s[3][3] = fmaf(a.w, b3, s[3][3]);
        }

        float p[4][4];
#pragma unroll
        for (int i = 0; i < 4; i++) {
#pragma unroll
            for (int j = 0; j < 4; j++) s[i][j] *= ATT_SCALE;
            float mt = fmaxf(fmaxf(s[i][0], s[i][1]), fmaxf(s[i][2], s[i][3]));
#pragma unroll
            for (int off = 8; off >= 1; off >>= 1)
                mt = fmaxf(mt, __shfl_xor_sync(0xffffffffu, mt, off));
            float m_new = fmaxf(m_run[i], mt);
            float corr  = __expf(m_run[i] - m_new);
            m_run[i] = m_new;
            float rs = 0.f;
#pragma unroll
            for (int j = 0; j < 4; j++) {
                p[i][j] = __expf(s[i][j] - m_new);
                rs += p[i][j];
            }
#pragma unroll
            for (int off = 8; off >= 1; off >>= 1)
                rs += __shfl_xor_sync(0xffffffffu, rs, off);
            l_run[i] = l_run[i] * corr + rs;
#pragma unroll
            for (int j = 0; j < 4; j++) o[i][j] *= corr;
        }

        __syncthreads();
#pragma unroll
        for (int i = 0; i < 4; i++)
#pragma unroll
            for (int j = 0; j < 4; j++)
                KP[(ty * 4 + i) * 65 + tx * 4 + j] = p[i][j];
        __syncthreads();

#pragma unroll 8
        for (int c = 0; c < 64; c++) {
            float4 v = *(const float4*)&Vs[c * 64 + tx * 4];
            float p0 = KP[(ty * 4 + 0) * 65 + c];
            float p1 = KP[(ty * 4 + 1) * 65 + c];
            float p2 = KP[(ty * 4 + 2) * 65 + c];
            float p3 = KP[(ty * 4 + 3) * 65 + c];
            o[0][0] = fmaf(p0, v.x, o[0][0]); o[0][1] = fmaf(p0, v.y, o[0][1]);
            o[0][2] = fmaf(p0, v.z, o[0][2]); o[0][3] = fmaf(p0, v.w, o[0][3]);
            o[1][0] = fmaf(p1, v.x, o[1][0]); o[1][1] = fmaf(p1, v.y, o[1][1]);
            o[1][2] = fmaf(p1, v.z, o[1][2]); o[1][3] = fmaf(p1, v.w, o[1][3]);
            o[2][0] = fmaf(p2, v.x, o[2][0]); o[2][1] = fmaf(p2, v.y, o[2][1]);
            o[2][2] = fmaf(p2, v.z, o[2][2]); o[2][3] = fmaf(p2, v.w, o[2][3]);
            o[3][0] = fmaf(p3, v.x, o[3][0]); o[3][1] = fmaf(p3, v.y, o[3][1]);
            o[3][2] = fmaf(p3, v.z, o[3][2]); o[3][3] = fmaf(p3, v.w, o[3][3]);
        }
    }

#pragma unroll
    for (int i = 0; i < 4; i++) {
        float inv = 1.f / l_run[i];
        float4 ov;
        ov.x = o[i][0] * inv; ov.y = o[i][1] * inv;
        ov.z = o[i][2] * inv; ov.w = o[i][3] * inv;
        *(float4*)(out + (b * NSEQ + q0 + ty * 4 + i) * C_DIM + h * HDIM + tx * 4) = ov;
    }
}

// ---------------------------------------------------------------------------
extern "C" void kernel_launch(void* const* d_in, const int* in_sizes, int n_in,
                              void* d_out, int out_size)
{
    const float* x      = (const float*)d_in[0];
    const float* w_qkv  = (const float*)d_in[1];
    const float* b_qkv  = (const float*)d_in[2];
    const float* w_proj = (const float*)d_in[3];
    const float* b_proj = (const float*)d_in[4];
    float* out = (float*)d_out;

    float *qkv_s, *att_s;
    cudaGetSymbolAddress((void**)&qkv_s, g_qkv);
    cudaGetSymbolAddress((void**)&att_s, g_att);

    const int attn_smem = (64 * 64 + 64 * 65 + 64 * 64) * (int)sizeof(float);
    cudaFuncSetAttribute(attn_kernel, cudaFuncAttributeMaxDynamicSharedMemorySize, attn_smem);
    cudaFuncSetAttribute(gemm_mma_tf32, cudaFuncAttributeMaxDynamicSharedMemorySize, GEMM_SMEM);

    // 1) QKV projection: [4096,1024] @ [3072,1024]^T + b -> [4096,3072]
    dim3 g1(3 * C_DIM / 128, ROWS / 128);
    gemm_mma_tf32<<<g1, 256, GEMM_SMEM>>>(x, w_qkv, b_qkv, qkv_s, ROWS, 3 * C_DIM, C_DIM);

    // 2) Fused attention -> [4096,1024]
    dim3 g2(NSEQ / 64, BATCH * NHEADS);
    attn_kernel<<<g2, 256, attn_smem>>>(qkv_s, att_s);

    // 3) Output projection: [4096,1024] @ [1024,1024]^T + b -> out
    dim3 g3(C_DIM / 128, ROWS / 128);
    gemm_mma_tf32<<<g3, 256, GEMM_SMEM>>>(att_s, w_proj, b_proj, out, ROWS, C_DIM, C_DIM);
}

// round 4
// speedup vs baseline: 2.9821x; 2.2776x over previous
#include <cuda_runtime.h>
#include <cstdint>

#define C_DIM   1024
#define NSEQ    2048
#define NHEADS  16
#define HDIM    64
#define BATCH   2
#define ROWS    (BATCH * NSEQ)       // 4096
#define ATT_SCALE 0.125f             // 1/sqrt(64)

// Scratch (no allocations allowed in kernel_launch)
__device__ float g_qkv[ROWS * 3 * C_DIM];   // [4096, 3072]
__device__ float g_att[ROWS * C_DIM];       // [4096, 1024]

// ===========================================================================
// tf32 helpers (arch-independent PTX)
// ===========================================================================
__device__ __forceinline__ uint32_t f2tf32(float x) {
    uint32_t r;
    asm("cvt.rna.tf32.f32 %0, %1;" : "=r"(r) : "f"(x));
    return r;
}

// D += A @ B  for one m16n8k8 tf32 tile.
// lane = r*4 + c (r = lane>>2, c = lane&3):
//   a0=A[r][c] a1=A[r+8][c] a2=A[r][c+4] a3=A[r+8][c+4]
//   b0=B[k=c][n=r] b1=B[k=c+4][n=r]
//   d0=C[r][2c] d1=C[r][2c+1] d2=C[r+8][2c] d3=C[r+8][2c+1]
__device__ __forceinline__ void mma_tf32(float* d, const uint32_t* a, const uint32_t* b) {
    asm volatile(
        "mma.sync.aligned.m16n8k8.row.col.f32.tf32.tf32.f32 "
        "{%0,%1,%2,%3}, {%4,%5,%6,%7}, {%8,%9}, {%0,%1,%2,%3};"
        : "+f"(d[0]), "+f"(d[1]), "+f"(d[2]), "+f"(d[3])
        : "r"(a[0]), "r"(a[1]), "r"(a[2]), "r"(a[3]), "r"(b[0]), "r"(b[1]));
}

// ===========================================================================
// tf32 mma.sync NT GEMM:  C[M,Nt] = A[M,K] @ W[Nt,K]^T + bias[Nt]
// 128x128 tile, BK=32, 256 threads (8 warps, 64x32 each), 2 CTAs/SM.
// Plain smem layout with pitch 36 (36 mod 32 == 4 -> frag LDS conflict-free).
// Single __syncthreads per chunk (store into opposite buffer pre-sync).
// ===========================================================================
#define GP 36
#define GSTAGE_F (2 * 128 * GP)          // A + B per stage (floats)
#define GEMM_SMEM (2 * GSTAGE_F * 4)     // 73728 B

__global__ __launch_bounds__(256, 2)
void gemm_mma_tf32(const float* __restrict__ A, const float* __restrict__ W,
                   const float* __restrict__ bias, float* __restrict__ Cout,
                   int M, int Nt, int K)
{
    extern __shared__ float smf[];
    const int t      = threadIdx.x;
    const int lane   = t & 31;
    const int r      = lane >> 2;
    const int cq     = lane & 3;
    const int wid    = t >> 5;
    const int warp_m = wid & 1;     // 2 warps over M (64 rows each)
    const int warp_n = wid >> 1;    // 4 warps over N (32 cols each)
    const int m0 = blockIdx.y << 7;
    const int n0 = blockIdx.x << 7;

    float acc[4][4][4];
#pragma unroll
    for (int i = 0; i < 4; i++)
#pragma unroll
        for (int j = 0; j < 4; j++)
#pragma unroll
            for (int e = 0; e < 4; e++) acc[i][j][e] = 0.f;

    const int nch = K / 32;
    const int grow = t >> 3;              // 0..31 (×4 via p)
    const int gc4  = (t & 7) << 2;        // 0..28

    float4 ra[4], rw[4];

#define LOAD_GMEM(cidx)                                                        \
    {                                                                          \
        const float* Ap = A + (size_t)m0 * K + (cidx) * 32;                    \
        const float* Wp = W + (size_t)n0 * K + (cidx) * 32;                    \
        _Pragma("unroll")                                                      \
        for (int p = 0; p < 4; p++) {                                          \
            int row = grow + p * 32;                                           \
            ra[p] = *(const float4*)(Ap + (size_t)row * K + gc4);              \
            rw[p] = *(const float4*)(Wp + (size_t)row * K + gc4);              \
        }                                                                      \
    }

#define STORE_STAGE(s)                                                         \
    {                                                                          \
        float* As = smf + (s) * GSTAGE_F;                                      \
        float* Bs = As + 128 * GP;                                             \
        _Pragma("unroll")                                                      \
        for (int p = 0; p < 4; p++) {                                          \
            int row = grow + p * 32;                                           \
            uint4 ua = make_uint4(f2tf32(ra[p].x), f2tf32(ra[p].y),            \
                                  f2tf32(ra[p].z), f2tf32(ra[p].w));           \
            uint4 uw = make_uint4(f2tf32(rw[p].x), f2tf32(rw[p].y),            \
                                  f2tf32(rw[p].z), f2tf32(rw[p].w));           \
            *(uint4*)&As[row * GP + gc4] = ua;                                 \
            *(uint4*)&Bs[row * GP + gc4] = uw;                                 \
        }                                                                      \
    }

    LOAD_GMEM(0);
    STORE_STAGE(0);
    __syncthreads();

    for (int c = 0; c < nch; c++) {
        const int s = c & 1;
        if (c + 1 < nch) LOAD_GMEM(c + 1);

        const float* As = smf + s * GSTAGE_F;
        const float* Bs = As + 128 * GP;
#pragma unroll
        for (int ks = 0; ks < 4; ks++) {
            uint32_t afr[4][4], bfr[4][2];
#pragma unroll
            for (int mt = 0; mt < 4; mt++) {
                const float* Ab = As + (warp_m * 64 + mt * 16) * GP + ks * 8;
                afr[mt][0] = __float_as_uint(Ab[r * GP + cq]);
                afr[mt][1] = __float_as_uint(Ab[(r + 8) * GP + cq]);
                afr[mt][2] = __float_as_uint(Ab[r * GP + cq + 4]);
                afr[mt][3] = __float_as_uint(Ab[(r + 8) * GP + cq + 4]);
            }
#pragma unroll
            for (int nt = 0; nt < 4; nt++) {
                const float* Bb = Bs + (warp_n * 32 + nt * 8 + r) * GP + ks * 8;
                bfr[nt][0] = __float_as_uint(Bb[cq]);
                bfr[nt][1] = __float_as_uint(Bb[cq + 4]);
            }
#pragma unroll
            for (int mt = 0; mt < 4; mt++)
#pragma unroll
                for (int nt = 0; nt < 4; nt++)
                    mma_tf32(acc[mt][nt], afr[mt], bfr[nt]);
        }

        if (c + 1 < nch) STORE_STAGE(s ^ 1);   // opposite buffer: safe pre-sync
        __syncthreads();
    }

    // Epilogue: direct stores with bias
    const int c2 = cq << 1;
#pragma unroll
    for (int nt = 0; nt < 4; nt++) {
        const int gn = n0 + warp_n * 32 + nt * 8 + c2;
        const float b0 = bias[gn], b1 = bias[gn + 1];
#pragma unroll
        for (int mt = 0; mt < 4; mt++) {
            const int gm = m0 + warp_m * 64 + mt * 16 + r;
            float2 v0, v1;
            v0.x = acc[mt][nt][0] + b0; v0.y = acc[mt][nt][1] + b1;
            v1.x = acc[mt][nt][2] + b0; v1.y = acc[mt][nt][3] + b1;
            *(float2*)&Cout[(size_t)gm * Nt + gn]       = v0;
            *(float2*)&Cout[(size_t)(gm + 8) * Nt + gn] = v1;
        }
    }
#undef LOAD_GMEM
#undef STORE_STAGE
}

// ===========================================================================
// Flash attention with tf32 mma.sync.
// Block: 256 queries x one (b,h). 512 threads = 16 warps; warp owns 16 rows.
// Loops over 32 key tiles of 64 (double-buffered K/V, 1 barrier per tile).
// smem (floats): Qs[256][68] tf32 | K0/K1[64][68] tf32 | V0/V1[64][72] tf32 |
//                Ps[256][68] tf32
// ===========================================================================
#define AQ      256
#define AP      68
#define VP      72
#define OFF_K0  (AQ * AP)                    // 17408
#define OFF_V0  (OFF_K0 + 64 * AP)           // 21760
#define OFF_K1  (OFF_V0 + 64 * VP)           // 26368
#define OFF_V1  (OFF_K1 + 64 * AP)           // 30720
#define OFF_PS  (OFF_V1 + 64 * VP)           // 35328
#define ATTN_SMEM ((OFF_PS + AQ * AP) * 4)   // 210944 B

__global__ __launch_bounds__(512)
void attn_mma(const float* __restrict__ qkv, float* __restrict__ out)
{
    extern __shared__ float sm[];
    const int t    = threadIdx.x;
    const int lane = t & 31;
    const int wid  = t >> 5;
    const int r    = lane >> 2;
    const int cq   = lane & 3;
    const int q0   = blockIdx.x * AQ;
    const int b    = blockIdx.y >> 4;
    const int h    = blockIdx.y & 15;
    const int rs   = 3 * C_DIM;

    const float* qb = qkv + ((size_t)(b * NSEQ + q0) * 3) * C_DIM + h * HDIM;
    const float* kb = qkv + ((size_t)(b * NSEQ) * 3 + 1) * C_DIM + h * HDIM;
    const float* vb = qkv + ((size_t)(b * NSEQ) * 3 + 2) * C_DIM + h * HDIM;

    // ---- stage Q (tf32) ----
#pragma unroll
    for (int p = 0; p < 8; p++) {
        int fi  = t + 512 * p;
        int row = fi >> 4;
        int d4  = (fi & 15) << 2;
        float4 v = *(const float4*)(qb + (size_t)row * rs + d4);
        uint4 u = make_uint4(f2tf32(v.x), f2tf32(v.y), f2tf32(v.z), f2tf32(v.w));
        *(uint4*)&sm[row * AP + d4] = u;
    }

    // K/V staging index (2 float4 each per thread)
    const int krow0 = t >> 4;              // 0..31
    const int krow1 = krow0 + 32;
    const int kd4   = (t & 15) << 2;

    // ---- stage K/V tile 0 ----
    {
        float4 k0 = *(const float4*)(kb + (size_t)krow0 * rs + kd4);
        float4 k1 = *(const float4*)(kb + (size_t)krow1 * rs + kd4);
        float4 v0 = *(const float4*)(vb + (size_t)krow0 * rs + kd4);
        float4 v1 = *(const float4*)(vb + (size_t)krow1 * rs + kd4);
        *(uint4*)&sm[OFF_K0 + krow0 * AP + kd4] =
            make_uint4(f2tf32(k0.x), f2tf32(k0.y), f2tf32(k0.z), f2tf32(k0.w));
        *(uint4*)&sm[OFF_K0 + krow1 * AP + kd4] =
            make_uint4(f2tf32(k1.x), f2tf32(k1.y), f2tf32(k1.z), f2tf32(k1.w));
        *(uint4*)&sm[OFF_V0 + krow0 * VP + kd4] =
            make_uint4(f2tf32(v0.x), f2tf32(v0.y), f2tf32(v0.z), f2tf32(v0.w));
        *(uint4*)&sm[OFF_V0 + krow1 * VP + kd4] =
            make_uint4(f2tf32(v1.x), f2tf32(v1.y), f2tf32(v1.z), f2tf32(v1.w));
    }
    __syncthreads();

    float o_[8][4];
#pragma unroll
    for (int nt = 0; nt < 8; nt++)
#pragma unroll
        for (int e = 0; e < 4; e++) o_[nt][e] = 0.f;
    float m0r = -1e30f, m1r = -1e30f, l0r = 0.f, l1r = 0.f;

    const int wrow = wid * 16;   // warp's query-row base within block

    for (int kt = 0; kt < NSEQ / 64; kt++) {
        const int s = kt & 1;
        const int koff = s ? OFF_K1 : OFF_K0;
        const int voff = s ? OFF_V1 : OFF_V0;

        // ---- S = Q @ K^T (warp: 16 rows x 64 cols) ----
        float s_[8][4];
#pragma unroll
        for (int nt = 0; nt < 8; nt++)
#pragma unroll
            for (int e = 0; e < 4; e++) s_[nt][e] = 0.f;

#pragma unroll
        for (int ks = 0; ks < 8; ks++) {
            uint32_t a[4];
            const float* Qb = &sm[wrow * AP + ks * 8];
            a[0] = __float_as_uint(Qb[r * AP + cq]);
            a[1] = __float_as_uint(Qb[(r + 8) * AP + cq]);
            a[2] = __float_as_uint(Qb[r * AP + cq + 4]);
            a[3] = __float_as_uint(Qb[(r + 8) * AP + cq + 4]);
#pragma unroll
            for (int nt = 0; nt < 8; nt++) {
                uint32_t bf[2];
                const float* Kb = &sm[koff + (nt * 8 + r) * AP + ks * 8];
                bf[0] = __float_as_uint(Kb[cq]);
                bf[1] = __float_as_uint(Kb[cq + 4]);
                mma_tf32(s_[nt], a, bf);
            }
        }

        // ---- prefetch next K/V tile (hidden behind softmax + PV) ----
        float4 pk0, pk1, pv0, pv1;
        if (kt + 1 < NSEQ / 64) {
            const float* kn = kb + (size_t)((kt + 1) * 64) * rs;
            const float* vn = vb + (size_t)((kt + 1) * 64) * rs;
            pk0 = *(const float4*)(kn + (size_t)krow0 * rs + kd4);
            pk1 = *(const float4*)(kn + (size_t)krow1 * rs + kd4);
            pv0 = *(const float4*)(vn + (size_t)krow0 * rs + kd4);
            pv1 = *(const float4*)(vn + (size_t)krow1 * rs + kd4);
        }

        // ---- online softmax (rows r and r+8; reduce over c-quad) ----
        float ml0 = -1e30f, ml1 = -1e30f;
#pragma unroll
        for (int nt = 0; nt < 8; nt++) {
            s_[nt][0] *= ATT_SCALE; s_[nt][1] *= ATT_SCALE;
            s_[nt][2] *= ATT_SCALE; s_[nt][3] *= ATT_SCALE;
            ml0 = fmaxf(ml0, fmaxf(s_[nt][0], s_[nt][1]));
            ml1 = fmaxf(ml1, fmaxf(s_[nt][2], s_[nt][3]));
        }
        ml0 = fmaxf(ml0, __shfl_xor_sync(0xffffffffu, ml0, 1));
        ml0 = fmaxf(ml0, __shfl_xor_sync(0xffffffffu, ml0, 2));
        ml1 = fmaxf(ml1, __shfl_xor_sync(0xffffffffu, ml1, 1));
        ml1 = fmaxf(ml1, __shfl_xor_sync(0xffffffffu, ml1, 2));

        float mn0 = fmaxf(m0r, ml0), mn1 = fmaxf(m1r, ml1);
        float cr0 = __expf(m0r - mn0), cr1 = __expf(m1r - mn1);
        m0r = mn0; m1r = mn1;

        float rs0 = 0.f, rs1 = 0.f;
#pragma unroll
        for (int nt = 0; nt < 8; nt++) {
            s_[nt][0] = __expf(s_[nt][0] - mn0);
            s_[nt][1] = __expf(s_[nt][1] - mn0);
            s_[nt][2] = __expf(s_[nt][2] - mn1);
            s_[nt][3] = __expf(s_[nt][3] - mn1);
            rs0 += s_[nt][0] + s_[nt][1];
            rs1 += s_[nt][2] + s_[nt][3];
        }
        rs0 += __shfl_xor_sync(0xffffffffu, rs0, 1);
        rs0 += __shfl_xor_sync(0xffffffffu, rs0, 2);
        rs1 += __shfl_xor_sync(0xffffffffu, rs1, 1);
        rs1 += __shfl_xor_sync(0xffffffffu, rs1, 2);
        l0r = l0r * cr0 + rs0;
        l1r = l1r * cr1 + rs1;

#pragma unroll
        for (int nt = 0; nt < 8; nt++) {
            o_[nt][0] *= cr0; o_[nt][1] *= cr0;
            o_[nt][2] *= cr1; o_[nt][3] *= cr1;
        }

        // ---- write P (tf32) to warp-private rows of Ps ----
#pragma unroll
        for (int nt = 0; nt < 8; nt++) {
            uint2 p01 = make_uint2(f2tf32(s_[nt][0]), f2tf32(s_[nt][1]));
            uint2 p23 = make_uint2(f2tf32(s_[nt][2]), f2tf32(s_[nt][3]));
            *(uint2*)&sm[OFF_PS + (wrow + r) * AP + nt * 8 + 2 * cq]     = p01;
            *(uint2*)&sm[OFF_PS + (wrow + r + 8) * AP + nt * 8 + 2 * cq] = p23;
        }
        __syncwarp();

        // ---- O += P @ V ----
#pragma unroll
        for (int ks = 0; ks < 8; ks++) {
            uint32_t a[4];
            const float* Pb = &sm[OFF_PS + wrow * AP + ks * 8];
            a[0] = __float_as_uint(Pb[r * AP + cq]);
            a[1] = __float_as_uint(Pb[(r + 8) * AP + cq]);
            a[2] = __float_as_uint(Pb[r * AP + cq + 4]);
            a[3] = __float_as_uint(Pb[(r + 8) * AP + cq + 4]);
#pragma unroll
            for (int nt = 0; nt < 8; nt++) {
                uint32_t bf[2];
                const float* Vb = &sm[voff + (ks * 8 + cq) * VP + nt * 8 + r];
                bf[0] = __float_as_uint(Vb[0]);
                bf[1] = __float_as_uint(Vb[4 * VP]);
                mma_tf32(o_[nt], a, bf);
            }
        }

        // ---- stage next tile into opposite buffer, then one barrier ----
        if (kt + 1 < NSEQ / 64) {
            const int nk = s ? OFF_K0 : OFF_K1;
            const int nv = s ? OFF_V0 : OFF_V1;
            *(uint4*)&sm[nk + krow0 * AP + kd4] =
                make_uint4(f2tf32(pk0.x), f2tf32(pk0.y), f2tf32(pk0.z), f2tf32(pk0.w));
            *(uint4*)&sm[nk + krow1 * AP + kd4] =
                make_uint4(f2tf32(pk1.x), f2tf32(pk1.y), f2tf32(pk1.z), f2tf32(pk1.w));
            *(uint4*)&sm[nv + krow0 * VP + kd4] =
                make_uint4(f2tf32(pv0.x), f2tf32(pv0.y), f2tf32(pv0.z), f2tf32(pv0.w));
            *(uint4*)&sm[nv + krow1 * VP + kd4] =
                make_uint4(f2tf32(pv1.x), f2tf32(pv1.y), f2tf32(pv1.z), f2tf32(pv1.w));
        }
        __syncthreads();
    }

    // ---- epilogue: normalize, store to [4096,1024] ----
    const float i0 = 1.f / l0r, i1 = 1.f / l1r;
#pragma unroll
    for (int nt = 0; nt < 8; nt++) {
        const int col = h * HDIM + nt * 8 + 2 * cq;
        float2 v0, v1;
        v0.x = o_[nt][0] * i0; v0.y = o_[nt][1] * i0;
        v1.x = o_[nt][2] * i1; v1.y = o_[nt][3] * i1;
        *(float2*)&out[(size_t)(b * NSEQ + q0 + wrow + r) * C_DIM + col]     = v0;
        *(float2*)&out[(size_t)(b * NSEQ + q0 + wrow + r + 8) * C_DIM + col] = v1;
    }
}

// ---------------------------------------------------------------------------
extern "C" void kernel_launch(void* const* d_in, const int* in_sizes, int n_in,
                              void* d_out, int out_size)
{
    const float* x      = (const float*)d_in[0];
    const float* w_qkv  = (const float*)d_in[1];
    const float* b_qkv  = (const float*)d_in[2];
    const float* w_proj = (const float*)d_in[3];
    const float* b_proj = (const float*)d_in[4];
    float* out = (float*)d_out;

    float *qkv_s, *att_s;
    cudaGetSymbolAddress((void**)&qkv_s, g_qkv);
    cudaGetSymbolAddress((void**)&att_s, g_att);

    cudaFuncSetAttribute(gemm_mma_tf32, cudaFuncAttributeMaxDynamicSharedMemorySize, GEMM_SMEM);
    cudaFuncSetAttribute(attn_mma, cudaFuncAttributeMaxDynamicSharedMemorySize, ATTN_SMEM);

    // 1) QKV projection: [4096,1024] @ [3072,1024]^T + b -> [4096,3072]
    dim3 g1(3 * C_DIM / 128, ROWS / 128);
    gemm_mma_tf32<<<g1, 256, GEMM_SMEM>>>(x, w_qkv, b_qkv, qkv_s, ROWS, 3 * C_DIM, C_DIM);

    // 2) Fused attention -> [4096,1024]
    dim3 g2(NSEQ / AQ, BATCH * NHEADS);
    attn_mma<<<g2, 512, ATTN_SMEM>>>(qkv_s, att_s);

    // 3) Output projection: [4096,1024] @ [1024,1024]^T + b -> out
    dim3 g3(C_DIM / 128, ROWS / 128);
    gemm_mma_tf32<<<g3, 256, GEMM_SMEM>>>(att_s, w_proj, b_proj, out, ROWS, C_DIM, C_DIM);
}